// round 6
// baseline (speedup 1.0000x reference)
#include <cuda_runtime.h>
#include <cuda_bf16.h>
#include <cstdint>

#define BB 32768
#define IN 512
#define HID 256
#define OUT 128
#define NE 16
#define CTX 256
#define DEMO 16
#define GATE_IN 784

// ---------------- device scratch: bf16 hi/lo planes, packed 2-per-u32 along K ----------------
__device__ uint32_t g_xh[BB * IN / 2];            // x hi plane
__device__ uint32_t g_xl[BB * IN / 2];            // x lo plane
__device__ uint32_t g_w1h[NE * HID * IN / 2];
__device__ uint32_t g_w1l[NE * HID * IN / 2];
__device__ uint32_t g_w2h[NE * OUT * HID / 2];
__device__ uint32_t g_w2l[NE * OUT * HID / 2];
__device__ float    g_wgt[BB * NE];               // softmax gate weights

// ---------------- helpers ----------------
__device__ __forceinline__ void split2(float a, float b, uint32_t& hi, uint32_t& lo) {
    __nv_bfloat16 ah = __float2bfloat16(a);
    __nv_bfloat16 bh = __float2bfloat16(b);
    __nv_bfloat16 al = __float2bfloat16(a - __bfloat162float(ah));
    __nv_bfloat16 bl = __float2bfloat16(b - __bfloat162float(bh));
    hi = ((uint32_t)__bfloat16_as_ushort(bh) << 16) | __bfloat16_as_ushort(ah);
    lo = ((uint32_t)__bfloat16_as_ushort(bl) << 16) | __bfloat16_as_ushort(al);
}
__device__ __forceinline__ void cp16(void* s, const void* g) {
    uint32_t sa = (uint32_t)__cvta_generic_to_shared(s);
    asm volatile("cp.async.cg.shared.global [%0], [%1], 16;" :: "r"(sa), "l"(g));
}
__device__ __forceinline__ void cp_commit() { asm volatile("cp.async.commit_group;"); }
__device__ __forceinline__ void cp_wait0()  { asm volatile("cp.async.wait_group 0;" ::: "memory"); }

__device__ __forceinline__ void mma_bf16(float* c, const uint32_t* a,
                                         uint32_t b0, uint32_t b1) {
    asm volatile(
        "mma.sync.aligned.m16n8k16.row.col.f32.bf16.bf16.f32 "
        "{%0,%1,%2,%3},{%4,%5,%6,%7},{%8,%9},{%0,%1,%2,%3};\n"
        : "+f"(c[0]), "+f"(c[1]), "+f"(c[2]), "+f"(c[3])
        : "r"(a[0]), "r"(a[1]), "r"(a[2]), "r"(a[3]), "r"(b0), "r"(b1));
}

// ---------------- gate: logits + softmax + x split + W split (fused) ----------------
#define W1_F4 (NE * HID * IN / 4)
#define W2_F4 (NE * OUT * HID / 4)

__device__ __forceinline__ void gfma(float* acc, const float* gWs, int k, float v) {
    const float4* w = (const float4*)(gWs + k * 16);
    #pragma unroll
    for (int q = 0; q < 4; ++q) {
        float4 ww = w[q];
        acc[q * 4 + 0] += v * ww.x; acc[q * 4 + 1] += v * ww.y;
        acc[q * 4 + 2] += v * ww.z; acc[q * 4 + 3] += v * ww.w;
    }
}

__global__ __launch_bounds__(256) void gate_k(
    const float* __restrict__ u, const float* __restrict__ x,
    const float* __restrict__ d, const float* __restrict__ gW,
    const float* __restrict__ gb,
    const float* __restrict__ W1, const float* __restrict__ W2) {
    extern __shared__ float gWs[];  // [784][16] transposed
    int tid = threadIdx.x;

    // ---- folded W1/W2 hi/lo split (grid-stride) ----
    {
        int gtid = blockIdx.x * 256 + tid;
        int nthr = gridDim.x * 256;
        for (int i = gtid; i < W1_F4; i += nthr) {
            float4 v = ((const float4*)W1)[i];
            uint32_t h0, l0, h1, l1;
            split2(v.x, v.y, h0, l0);
            split2(v.z, v.w, h1, l1);
            g_w1h[2 * i] = h0; g_w1h[2 * i + 1] = h1;
            g_w1l[2 * i] = l0; g_w1l[2 * i + 1] = l1;
        }
        for (int i = gtid; i < W2_F4; i += nthr) {
            float4 v = ((const float4*)W2)[i];
            uint32_t h0, l0, h1, l1;
            split2(v.x, v.y, h0, l0);
            split2(v.z, v.w, h1, l1);
            g_w2h[2 * i] = h0; g_w2h[2 * i + 1] = h1;
            g_w2l[2 * i] = l0; g_w2l[2 * i + 1] = l1;
        }
    }

    for (int i = tid; i < GATE_IN * NE; i += 256) {
        int e = i / GATE_IN, k = i - e * GATE_IN;
        gWs[k * 16 + e] = gW[i];
    }
    __syncthreads();

    int r = blockIdx.x * 256 + tid;
    float acc[16];
    #pragma unroll
    for (int e = 0; e < 16; ++e) acc[e] = gb[e];

    const float4* u4 = (const float4*)(u + (size_t)r * CTX);
    const float4* x4 = (const float4*)(x + (size_t)r * IN);
    const float4* d4 = (const float4*)(d + (size_t)r * DEMO);

    int kb = 0;
    #pragma unroll 4
    for (int i = 0; i < CTX / 4; ++i) {
        float4 v = u4[i];
        gfma(acc, gWs, kb + 0, v.x); gfma(acc, gWs, kb + 1, v.y);
        gfma(acc, gWs, kb + 2, v.z); gfma(acc, gWs, kb + 3, v.w);
        kb += 4;
    }
    #pragma unroll 4
    for (int i = 0; i < IN / 4; ++i) {
        float4 v = x4[i];
        gfma(acc, gWs, kb + 0, v.x); gfma(acc, gWs, kb + 1, v.y);
        gfma(acc, gWs, kb + 2, v.z); gfma(acc, gWs, kb + 3, v.w);
        kb += 4;
        uint32_t h0, l0, h1, l1;
        split2(v.x, v.y, h0, l0);
        split2(v.z, v.w, h1, l1);
        size_t bidx = (size_t)r * (IN / 2) + 2 * i;
        g_xh[bidx] = h0; g_xh[bidx + 1] = h1;
        g_xl[bidx] = l0; g_xl[bidx + 1] = l1;
    }
    #pragma unroll
    for (int i = 0; i < DEMO / 4; ++i) {
        float4 v = d4[i];
        gfma(acc, gWs, kb + 0, v.x); gfma(acc, gWs, kb + 1, v.y);
        gfma(acc, gWs, kb + 2, v.z); gfma(acc, gWs, kb + 3, v.w);
        kb += 4;
    }

    float m = acc[0];
    #pragma unroll
    for (int e = 1; e < 16; ++e) m = fmaxf(m, acc[e]);
    float s = 0.f;
    #pragma unroll
    for (int e = 0; e < 16; ++e) { acc[e] = expf(acc[e] - m); s += acc[e]; }
    float inv = 1.f / s;
    #pragma unroll
    for (int e = 0; e < 16; ++e) g_wgt[(size_t)r * NE + e] = acc[e] * inv;
}

// ---------------- main fused MoE kernel (bf16x3 mma.sync, R5 pipeline) ----------------
// SMEM u32 layout (46080 u32 = 184320 B):
//   [0, 33792)        Hs hi plane [0,16896) + lo plane [16896,33792), 128 x 132 each
//     phase-A staging aliases: XA [0,10240) buf*5120+plane*2560 ; WA [10240,30720) buf*10240+plane*5120
//   [33792, 44032)    W2 staging: buf*5120 + plane*2560 (128 x 20 each)
//   [44032, 46080)    wts (float) 128 x 16
#define HS_HI   0
#define HS_LO   16896
#define HS_STRIDE 132
#define XA_OFF  0
#define XA_BUF  5120
#define XA_PL   2560
#define WA_OFF  10240
#define WA_BUF  10240
#define WA_PL   5120
#define W2_OFF  33792
#define W2_BUF  5120
#define W2_PL   2560
#define WTS_OFF 44032
#define SMEM_BYTES (46080 * 4)

__device__ __forceinline__ void stageA(uint32_t* sm, int tid, int b0, int e, int ci, int buf) {
    uint32_t* xh = sm + XA_OFF + buf * XA_BUF;
    uint32_t* xl = xh + XA_PL;
    uint32_t* wh = sm + WA_OFF + buf * WA_BUF;
    uint32_t* wl = wh + WA_PL;
    const uint32_t* xhs = g_xh + (size_t)b0 * (IN / 2) + ci * 16;
    const uint32_t* xls = g_xl + (size_t)b0 * (IN / 2) + ci * 16;
    const uint32_t* whs = g_w1h + (size_t)e * HID * (IN / 2) + ci * 16;
    const uint32_t* wls = g_w1l + (size_t)e * HID * (IN / 2) + ci * 16;
    #pragma unroll
    for (int j = 0; j < 2; ++j) {              // X: 128 rows x 16 u32, 2 planes
        int v = tid + j * 256;
        int r = v >> 2, q = (v & 3) * 4;
        cp16(xh + r * 20 + q, xhs + (size_t)r * (IN / 2) + q);
        cp16(xl + r * 20 + q, xls + (size_t)r * (IN / 2) + q);
    }
    #pragma unroll
    for (int j = 0; j < 4; ++j) {              // W1: 256 rows x 16 u32, 2 planes
        int v = tid + j * 256;
        int r = v >> 2, q = (v & 3) * 4;
        cp16(wh + r * 20 + q, whs + (size_t)r * (IN / 2) + q);
        cp16(wl + r * 20 + q, wls + (size_t)r * (IN / 2) + q);
    }
}
__device__ __forceinline__ void stageB(uint32_t* sm, int tid, int e, int ci, int buf) {
    uint32_t* wh = sm + W2_OFF + buf * W2_BUF;
    uint32_t* wl = wh + W2_PL;
    const uint32_t* whs = g_w2h + (size_t)e * OUT * (HID / 2) + ci * 16;
    const uint32_t* wls = g_w2l + (size_t)e * OUT * (HID / 2) + ci * 16;
    #pragma unroll
    for (int j = 0; j < 2; ++j) {              // W2: 128 rows x 16 u32, 2 planes
        int v = tid + j * 256;
        int r = v >> 2, q = (v & 3) * 4;
        cp16(wh + r * 20 + q, whs + (size_t)r * (HID / 2) + q);
        cp16(wl + r * 20 + q, wls + (size_t)r * (HID / 2) + q);
    }
}

__global__ __launch_bounds__(256, 1) void moe_main(
    const float* __restrict__ b1, const float* __restrict__ b2,
    float* __restrict__ out) {
    extern __shared__ uint32_t smu[];
    const int tid  = threadIdx.x;
    const int warp = tid >> 5, lane = tid & 31;
    const int g = lane >> 2, t = lane & 3;
    const int b0 = blockIdx.x * 128;

    float* wts = (float*)(smu + WTS_OFF);
    for (int i = tid; i < 128 * NE; i += 256) wts[i] = g_wgt[(size_t)b0 * NE + i];

    // warp tiling: 2 (M) x 4 (N)
    const int wm  = (warp & 1) * 64;
    const int wn1 = (warp >> 1) * 64;   // phase-A cols (HID=256)
    const int wn2 = (warp >> 1) * 32;   // phase-B cols (OUT=128)

    float acc2[4][4][4];
    #pragma unroll
    for (int a = 0; a < 4; ++a)
        #pragma unroll
        for (int b = 0; b < 4; ++b)
            #pragma unroll
            for (int c = 0; c < 4; ++c) acc2[a][b][c] = 0.f;

    __syncthreads();

    for (int e = 0; e < NE; ++e) {
        // ===== Phase A: H = relu(X @ W1_e^T + b1) * w  (K=512, 16 chunks of 32) =====
        float acc1[4][8][4];
        #pragma unroll
        for (int a = 0; a < 4; ++a)
            #pragma unroll
            for (int b = 0; b < 8; ++b)
                #pragma unroll
                for (int c = 0; c < 4; ++c) acc1[a][b][c] = 0.f;

        stageA(smu, tid, b0, e, 0, 0);
        cp_commit();

        for (int ci = 0; ci < 16; ++ci) {
            int cur = ci & 1;
            cp_wait0(); __syncthreads();
            if (ci < 15) { stageA(smu, tid, b0, e, ci + 1, cur ^ 1); cp_commit(); }
            const uint32_t* xh = smu + XA_OFF + cur * XA_BUF;
            const uint32_t* xl = xh + XA_PL;
            const uint32_t* wh = smu + WA_OFF + cur * WA_BUF;
            const uint32_t* wl = wh + WA_PL;
            #pragma unroll
            for (int ks = 0; ks < 2; ++ks) {
                const int pb = ks * 8;
                uint32_t ah[4][4], al[4][4];
                #pragma unroll
                for (int mf = 0; mf < 4; ++mf) {
                    int r = wm + mf * 16 + g;
                    ah[mf][0] = xh[r * 20 + pb + t];
                    ah[mf][1] = xh[(r + 8) * 20 + pb + t];
                    ah[mf][2] = xh[r * 20 + pb + t + 4];
                    ah[mf][3] = xh[(r + 8) * 20 + pb + t + 4];
                    al[mf][0] = xl[r * 20 + pb + t];
                    al[mf][1] = xl[(r + 8) * 20 + pb + t];
                    al[mf][2] = xl[r * 20 + pb + t + 4];
                    al[mf][3] = xl[(r + 8) * 20 + pb + t + 4];
                }
                #pragma unroll
                for (int nf = 0; nf < 8; ++nf) {
                    int n = wn1 + nf * 8 + g;
                    uint32_t bh0 = wh[n * 20 + pb + t];
                    uint32_t bh1 = wh[n * 20 + pb + t + 4];
                    uint32_t bl0 = wl[n * 20 + pb + t];
                    uint32_t bl1 = wl[n * 20 + pb + t + 4];
                    #pragma unroll
                    for (int mf = 0; mf < 4; ++mf) {
                        mma_bf16(acc1[mf][nf], ah[mf], bh0, bh1);
                        mma_bf16(acc1[mf][nf], al[mf], bh0, bh1);
                        mma_bf16(acc1[mf][nf], ah[mf], bl0, bl1);
                    }
                }
            }
            __syncthreads();
        }

        // prefetch W2 chunk0 (separate region; overlaps epilogue)
        stageB(smu, tid, e, 0, 0);
        cp_commit();

        // epilogue A: relu + bias + gate-weight scale, hi/lo split, store H planes
        #pragma unroll
        for (int mf = 0; mf < 4; ++mf) {
            int r0 = wm + mf * 16 + g, r1 = r0 + 8;
            float w0 = wts[r0 * NE + e], w1 = wts[r1 * NE + e];
            #pragma unroll
            for (int nf = 0; nf < 8; ++nf) {
                int c0 = wn1 + nf * 8 + 2 * t;
                int p  = c0 >> 1;
                float bb0 = b1[e * HID + c0], bb1 = b1[e * HID + c0 + 1];
                float v00 = fmaxf(acc1[mf][nf][0] + bb0, 0.f) * w0;
                float v01 = fmaxf(acc1[mf][nf][1] + bb1, 0.f) * w0;
                float v10 = fmaxf(acc1[mf][nf][2] + bb0, 0.f) * w1;
                float v11 = fmaxf(acc1[mf][nf][3] + bb1, 0.f) * w1;
                uint32_t h, l;
                split2(v00, v01, h, l);
                smu[HS_HI + r0 * HS_STRIDE + p] = h;
                smu[HS_LO + r0 * HS_STRIDE + p] = l;
                split2(v10, v11, h, l);
                smu[HS_HI + r1 * HS_STRIDE + p] = h;
                smu[HS_LO + r1 * HS_STRIDE + p] = l;
            }
        }

        // ===== Phase B: out += H_e @ W2_e^T  (K=256, 8 chunks of 32) =====
        for (int ci = 0; ci < 8; ++ci) {
            int cur = ci & 1;
            cp_wait0(); __syncthreads();   // W2[cur] ready; ci==0 also orders H stores
            if (ci < 7) { stageB(smu, tid, e, ci + 1, cur ^ 1); cp_commit(); }
            const uint32_t* w2h = smu + W2_OFF + cur * W2_BUF;
            const uint32_t* w2l = w2h + W2_PL;
            #pragma unroll
            for (int ks = 0; ks < 2; ++ks) {
                const int pb  = ci * 16 + ks * 8;   // global k-pair base into Hs
                const int pb2 = ks * 8;             // within W2 chunk tile
                uint32_t ah[4][4], al[4][4];
                #pragma unroll
                for (int mf = 0; mf < 4; ++mf) {
                    int r = wm + mf * 16 + g;
                    ah[mf][0] = smu[HS_HI + r * HS_STRIDE + pb + t];
                    ah[mf][1] = smu[HS_HI + (r + 8) * HS_STRIDE + pb + t];
                    ah[mf][2] = smu[HS_HI + r * HS_STRIDE + pb + t + 4];
                    ah[mf][3] = smu[HS_HI + (r + 8) * HS_STRIDE + pb + t + 4];
                    al[mf][0] = smu[HS_LO + r * HS_STRIDE + pb + t];
                    al[mf][1] = smu[HS_LO + (r + 8) * HS_STRIDE + pb + t];
                    al[mf][2] = smu[HS_LO + r * HS_STRIDE + pb + t + 4];
                    al[mf][3] = smu[HS_LO + (r + 8) * HS_STRIDE + pb + t + 4];
                }
                #pragma unroll
                for (int nf = 0; nf < 4; ++nf) {
                    int n = wn2 + nf * 8 + g;
                    uint32_t bh0 = w2h[n * 20 + pb2 + t];
                    uint32_t bh1 = w2h[n * 20 + pb2 + t + 4];
                    uint32_t bl0 = w2l[n * 20 + pb2 + t];
                    uint32_t bl1 = w2l[n * 20 + pb2 + t + 4];
                    #pragma unroll
                    for (int mf = 0; mf < 4; ++mf) {
                        mma_bf16(acc2[mf][nf], ah[mf], bh0, bh1);
                        mma_bf16(acc2[mf][nf], al[mf], bh0, bh1);
                        mma_bf16(acc2[mf][nf], ah[mf], bl0, bl1);
                    }
                }
            }
            __syncthreads();
        }
        // all warps done reading Hs; next expert's stageA may overwrite it
    }

    // ===== epilogue: out = acc2 + sum_e w[b,e] * b2[e,:] =====
    #pragma unroll
    for (int mf = 0; mf < 4; ++mf) {
        int r0 = wm + mf * 16 + g, r1 = r0 + 8;
        #pragma unroll
        for (int nf = 0; nf < 4; ++nf) {
            int c0 = wn2 + nf * 8 + 2 * t;
            float s0 = acc2[mf][nf][0], s1 = acc2[mf][nf][1];
            float s2 = acc2[mf][nf][2], s3 = acc2[mf][nf][3];
            #pragma unroll
            for (int e = 0; e < NE; ++e) {
                float bb0 = b2[e * OUT + c0], bb1 = b2[e * OUT + c0 + 1];
                float we0 = wts[r0 * NE + e], we1 = wts[r1 * NE + e];
                s0 += we0 * bb0; s1 += we0 * bb1;
                s2 += we1 * bb0; s3 += we1 * bb1;
            }
            out[(size_t)(b0 + r0) * OUT + c0]     = s0;
            out[(size_t)(b0 + r0) * OUT + c0 + 1] = s1;
            out[(size_t)(b0 + r1) * OUT + c0]     = s2;
            out[(size_t)(b0 + r1) * OUT + c0 + 1] = s3;
        }
    }
}

// ---------------- launch (2 kernels) ----------------
extern "C" void kernel_launch(void* const* d_in, const int* in_sizes, int n_in,
                              void* d_out, int out_size) {
    const float* x  = (const float*)d_in[0];
    const float* u  = (const float*)d_in[1];
    const float* dd = (const float*)d_in[2];
    const float* gW = (const float*)d_in[3];
    const float* gb = (const float*)d_in[4];
    const float* W1 = (const float*)d_in[5];
    const float* b1 = (const float*)d_in[6];
    const float* W2 = (const float*)d_in[7];
    const float* b2 = (const float*)d_in[8];
    float* out = (float*)d_out;

    cudaFuncSetAttribute(gate_k, cudaFuncAttributeMaxDynamicSharedMemorySize,
                         GATE_IN * NE * 4);
    cudaFuncSetAttribute(moe_main, cudaFuncAttributeMaxDynamicSharedMemorySize,
                         SMEM_BYTES);

    gate_k<<<BB / 256, 256, GATE_IN * NE * 4>>>(u, x, dd, gW, gb, W1, W2);
    moe_main<<<BB / 128, 256, SMEM_BYTES>>>(b1, b2, out);
}